// round 1
// baseline (speedup 1.0000x reference)
#include <cuda_runtime.h>
#include <math.h>

// Problem constants (fixed by the reference)
#define BATCH   2
#define SEQ     2048
#define EMB     512
#define HEADS   8
#define DHEAD   64
#define WINHALF 128         // WIN/2

#define M1 (BATCH*SEQ)      // 4096 rows
#define N1 (3*EMB)          // 1536 (qkv)
#define KDIM EMB            // 512

// Scratch: __device__ globals (no allocation allowed anywhere)
__device__ float g_qkv[(size_t)M1 * N1];   // [B,S, H*(q|k|v)*64]  ~25 MB
__device__ float g_ctx[(size_t)M1 * EMB];  // attention output [B,S,E] ~8 MB

// ---------------------------------------------------------------------------
// SGEMM: C[M,N] = A[M,K] @ B[K,N] + bias[N]
// 128x128 block tile, BK=8, 8x8 per thread, 256 threads, reg prefetch.
// Assumes M%128==0, N%128==0, K%8==0 (true for all our shapes).
// ---------------------------------------------------------------------------
__global__ __launch_bounds__(256, 2) void sgemm_bias_kernel(
    const float* __restrict__ A, const float* __restrict__ B,
    const float* __restrict__ bias, float* __restrict__ C,
    int M, int N, int K)
{
    __shared__ float As[8][132];   // transposed A tile, padded (conflict-free)
    __shared__ float Bs[8][128];

    const int tid = threadIdx.x;
    const int bx = blockIdx.x, by = blockIdx.y;
    const int tx = tid & 15, ty = tid >> 4;

    const int arow = tid >> 1;            // 0..127
    const int acol = (tid & 1) << 2;      // 0 or 4
    const int brow = tid >> 5;            // 0..7
    const int bcol = (tid & 31) << 2;     // 0..124

    const float* Ag = A + (size_t)(by * 128 + arow) * K + acol;
    const float* Bg = B + (size_t)brow * N + bx * 128 + bcol;

    float acc[8][8];
    #pragma unroll
    for (int i = 0; i < 8; i++)
        #pragma unroll
        for (int j = 0; j < 8; j++) acc[i][j] = 0.f;

    float4 a4 = *(const float4*)Ag;
    float4 b4 = *(const float4*)Bg;

    for (int k0 = 0; k0 < K; k0 += 8) {
        As[acol + 0][arow] = a4.x;
        As[acol + 1][arow] = a4.y;
        As[acol + 2][arow] = a4.z;
        As[acol + 3][arow] = a4.w;
        *(float4*)&Bs[brow][bcol] = b4;
        __syncthreads();

        if (k0 + 8 < K) {  // prefetch next tile into registers
            a4 = *(const float4*)(Ag + k0 + 8);
            b4 = *(const float4*)(Bg + (size_t)(k0 + 8) * N);
        }

        #pragma unroll
        for (int kk = 0; kk < 8; kk++) {
            float ar[8], br[8];
            *(float4*)&ar[0] = *(const float4*)&As[kk][ty * 8];
            *(float4*)&ar[4] = *(const float4*)&As[kk][ty * 8 + 4];
            *(float4*)&br[0] = *(const float4*)&Bs[kk][tx * 8];
            *(float4*)&br[4] = *(const float4*)&Bs[kk][tx * 8 + 4];
            #pragma unroll
            for (int i = 0; i < 8; i++)
                #pragma unroll
                for (int j = 0; j < 8; j++)
                    acc[i][j] += ar[i] * br[j];
        }
        __syncthreads();
    }

    // epilogue: add bias, write back
    #pragma unroll
    for (int i = 0; i < 8; i++) {
        const int row = by * 128 + ty * 8 + i;
        float* Crow = C + (size_t)row * N + bx * 128 + tx * 8;
        #pragma unroll
        for (int j = 0; j < 8; j += 4) {
            float4 v;
            v.x = acc[i][j + 0] + bias[bx * 128 + tx * 8 + j + 0];
            v.y = acc[i][j + 1] + bias[bx * 128 + tx * 8 + j + 1];
            v.z = acc[i][j + 2] + bias[bx * 128 + tx * 8 + j + 2];
            v.w = acc[i][j + 3] + bias[bx * 128 + tx * 8 + j + 3];
            *(float4*)(Crow + j) = v;
        }
    }
}

// ---------------------------------------------------------------------------
// Fused banded attention (flash-style).
// Block: 256 threads, handles one (b,h) x 64 query rows.
// 5 key tiles of 64 cover the [r-128, r+128] window for all rows in the tile.
// Online softmax; P staged through shared memory (reusing the K tile buffer).
// ---------------------------------------------------------------------------
__global__ __launch_bounds__(256) void attn_kernel(
    const float* __restrict__ qkv, const int* __restrict__ pmask,
    float* __restrict__ ctx)
{
    extern __shared__ float sm[];
    float (*Qs)[65] = (float(*)[65])sm;                   // 64x65
    float (*Ks)[65] = (float(*)[65])(sm + 64 * 65);       // 64x65 (reused for P)
    float (*Vs)[65] = (float(*)[65])(sm + 2 * 64 * 65);   // 64x65
    __shared__ float m_sh[64], l_sh[64];

    const int tid = threadIdx.x;
    const int tx = tid & 15, ty = tid >> 4;
    const int r0 = blockIdx.x * 64;
    const int b  = blockIdx.y >> 3;
    const int h  = blockIdx.y & 7;

    const float* base = qkv + (size_t)b * SEQ * N1 + h * (3 * DHEAD);

    // Load Q tile (pre-scaled by 1/sqrt(DH) = 0.125)
    for (int idx = tid; idx < 64 * 16; idx += 256) {
        const int row = idx >> 4;
        const int c4  = (idx & 15) << 2;
        float4 v = *(const float4*)(base + (size_t)(r0 + row) * N1 + c4);
        Qs[row][c4 + 0] = v.x * 0.125f;
        Qs[row][c4 + 1] = v.y * 0.125f;
        Qs[row][c4 + 2] = v.z * 0.125f;
        Qs[row][c4 + 3] = v.w * 0.125f;
    }
    if (tid < 64) { m_sh[tid] = -1e30f; l_sh[tid] = 0.f; }

    float o[4][4];
    #pragma unroll
    for (int i = 0; i < 4; i++)
        #pragma unroll
        for (int j = 0; j < 4; j++) o[i][j] = 0.f;

    int gri[4];
    #pragma unroll
    for (int i = 0; i < 4; i++) gri[i] = r0 + ty * 4 + i;

    for (int kt = 0; kt < 5; kt++) {
        const int c0 = r0 - WINHALF + kt * 64;
        if (c0 + 63 < 0 || c0 >= SEQ) continue;   // uniform across block

        __syncthreads();  // Q ready (first pass) / previous tile fully consumed

        // Load K,V tile (zero-fill out-of-range rows)
        for (int idx = tid; idx < 64 * 16; idx += 256) {
            const int row = idx >> 4;
            const int c4  = (idx & 15) << 2;
            const int gc = c0 + row;
            float4 kv = make_float4(0.f, 0.f, 0.f, 0.f);
            float4 vv = make_float4(0.f, 0.f, 0.f, 0.f);
            if (gc >= 0 && gc < SEQ) {
                kv = *(const float4*)(base + (size_t)gc * N1 + DHEAD + c4);
                vv = *(const float4*)(base + (size_t)gc * N1 + 2 * DHEAD + c4);
            }
            Ks[row][c4 + 0] = kv.x; Ks[row][c4 + 1] = kv.y;
            Ks[row][c4 + 2] = kv.z; Ks[row][c4 + 3] = kv.w;
            Vs[row][c4 + 0] = vv.x; Vs[row][c4 + 1] = vv.y;
            Vs[row][c4 + 2] = vv.z; Vs[row][c4 + 3] = vv.w;
        }
        __syncthreads();

        // S = Q @ K^T  (4x4 per thread)
        float s[4][4];
        #pragma unroll
        for (int i = 0; i < 4; i++)
            #pragma unroll
            for (int j = 0; j < 4; j++) s[i][j] = 0.f;

        #pragma unroll 8
        for (int k = 0; k < 64; k++) {
            float ar[4], br[4];
            #pragma unroll
            for (int i = 0; i < 4; i++) ar[i] = Qs[ty * 4 + i][k];
            #pragma unroll
            for (int j = 0; j < 4; j++) br[j] = Ks[tx * 4 + j][k];
            #pragma unroll
            for (int i = 0; i < 4; i++)
                #pragma unroll
                for (int j = 0; j < 4; j++)
                    s[i][j] += ar[i] * br[j];
        }

        // Band + padding mask
        int gcj[4]; bool cv[4];
        #pragma unroll
        for (int j = 0; j < 4; j++) {
            gcj[j] = c0 + tx * 4 + j;
            cv[j] = (gcj[j] >= 0) && (gcj[j] < SEQ) &&
                    (pmask[b * SEQ + gcj[j]] == 1);
        }
        #pragma unroll
        for (int i = 0; i < 4; i++)
            #pragma unroll
            for (int j = 0; j < 4; j++) {
                const int d = gcj[j] - gri[i];
                if (!cv[j] || d > WINHALF || d < -WINHALF) s[i][j] = -1e30f;
            }

        // Online softmax per row (16 lanes with same ty own a row group)
        float p[4][4];
        #pragma unroll
        for (int i = 0; i < 4; i++) {
            const int row = ty * 4 + i;
            float tm = fmaxf(fmaxf(s[i][0], s[i][1]), fmaxf(s[i][2], s[i][3]));
            #pragma unroll
            for (int off = 8; off >= 1; off >>= 1)
                tm = fmaxf(tm, __shfl_xor_sync(0xffffffffu, tm, off));
            const float mo = m_sh[row];
            const float mn = fmaxf(mo, tm);
            const float sc = __expf(mo - mn);     // underflows to 0 when mo=-1e30
            float ts = 0.f;
            #pragma unroll
            for (int j = 0; j < 4; j++) {
                p[i][j] = (s[i][j] > -1e29f) ? __expf(s[i][j] - mn) : 0.f;
                ts += p[i][j];
            }
            #pragma unroll
            for (int off = 8; off >= 1; off >>= 1)
                ts += __shfl_xor_sync(0xffffffffu, ts, off);
            if (tx == 0) { m_sh[row] = mn; l_sh[row] = l_sh[row] * sc + ts; }
            #pragma unroll
            for (int j = 0; j < 4; j++) o[i][j] *= sc;
        }

        __syncthreads();   // everyone done reading Ks; safe to overwrite with P
        #pragma unroll
        for (int i = 0; i < 4; i++)
            #pragma unroll
            for (int j = 0; j < 4; j++)
                Ks[ty * 4 + i][tx * 4 + j] = p[i][j];
        __syncthreads();

        // O += P @ V  (4 rows x 4 dims per thread)
        #pragma unroll 8
        for (int c = 0; c < 64; c++) {
            float pr[4], vr[4];
            #pragma unroll
            for (int i = 0; i < 4; i++) pr[i] = Ks[ty * 4 + i][c];
            #pragma unroll
            for (int j = 0; j < 4; j++) vr[j] = Vs[c][tx * 4 + j];
            #pragma unroll
            for (int i = 0; i < 4; i++)
                #pragma unroll
                for (int j = 0; j < 4; j++)
                    o[i][j] += pr[i] * vr[j];
        }
    }
    __syncthreads();

    // Normalize and write [B,S,H,DH] -> ctx [B,S,E]
    #pragma unroll
    for (int i = 0; i < 4; i++) {
        const int row = r0 + ty * 4 + i;
        const float l = l_sh[ty * 4 + i];
        const float inv = (l > 0.f && pmask[b * SEQ + row] == 1) ? 1.f / l : 0.f;
        float4 v;
        v.x = o[i][0] * inv; v.y = o[i][1] * inv;
        v.z = o[i][2] * inv; v.w = o[i][3] * inv;
        *(float4*)(ctx + (size_t)(b * SEQ + row) * EMB + h * DHEAD + tx * 4) = v;
    }
}

// ---------------------------------------------------------------------------
// Launch
// ---------------------------------------------------------------------------
extern "C" void kernel_launch(void* const* d_in, const int* in_sizes, int n_in,
                              void* d_out, int out_size)
{
    const float* x     = (const float*)d_in[0];
    const int*   pmask = (const int*)  d_in[1];
    const float* Wqkv  = (const float*)d_in[2];
    const float* bqkv  = (const float*)d_in[3];
    const float* Wo    = (const float*)d_in[4];
    const float* bo    = (const float*)d_in[5];
    float* out = (float*)d_out;

    float *qkv, *ctx;
    cudaGetSymbolAddress((void**)&qkv, g_qkv);
    cudaGetSymbolAddress((void**)&ctx, g_ctx);

    // 1) QKV projection: [4096,512] @ [512,1536] + bqkv
    {
        dim3 grid(N1 / 128, M1 / 128);
        sgemm_bias_kernel<<<grid, 256>>>(x, Wqkv, bqkv, qkv, M1, N1, KDIM);
    }

    // 2) Banded attention
    {
        const int smem = 3 * 64 * 65 * (int)sizeof(float);  // 49,920 B
        cudaFuncSetAttribute(attn_kernel,
                             cudaFuncAttributeMaxDynamicSharedMemorySize, smem);
        dim3 grid(SEQ / 64, BATCH * HEADS);
        attn_kernel<<<grid, 256, smem>>>(qkv, pmask, ctx);
    }

    // 3) Output projection: [4096,512] @ [512,512] + bo
    {
        dim3 grid(EMB / 128, M1 / 128);
        sgemm_bias_kernel<<<grid, 256>>>(ctx, Wo, bo, out, M1, EMB, KDIM);
    }
}

// round 8
// speedup vs baseline: 1.7091x; 1.7091x over previous
#include <cuda_runtime.h>
#include <cstdint>
#include <math.h>

// Problem constants (fixed by the reference)
#define BATCH   2
#define SEQ     2048
#define EMB     512
#define HEADS   8
#define DHEAD   64
#define WINHALF 128         // WIN/2

#define M1 (BATCH*SEQ)      // 4096 rows
#define N1 (3*EMB)          // 1536 (qkv)
#define KDIM EMB            // 512

// Scratch: __device__ globals (no allocation allowed anywhere)
__device__ float g_qkv[(size_t)M1 * N1];     // [B,S, H*(q|k|v)*64]  ~25 MB
__device__ float g_ctx[(size_t)M1 * EMB];    // attention output [B,S,E] ~8 MB

// ===========================================================================
// Helpers: mma.sync tf32 (SM80-compatible path, valid on compute_100)
// ===========================================================================
__device__ __forceinline__ uint32_t f2tf32(float x) {
    uint32_t r;
    asm("cvt.rna.tf32.f32 %0, %1;" : "=r"(r) : "f"(x));
    return r;
}

__device__ __forceinline__ void mma_tf32_16x8x8(
    float* c, uint32_t a0, uint32_t a1, uint32_t a2, uint32_t a3,
    uint32_t b0, uint32_t b1)
{
    asm volatile(
        "mma.sync.aligned.m16n8k8.row.col.f32.tf32.tf32.f32 "
        "{%0,%1,%2,%3}, {%4,%5,%6,%7}, {%8,%9}, {%0,%1,%2,%3};"
        : "+f"(c[0]), "+f"(c[1]), "+f"(c[2]), "+f"(c[3])
        : "r"(a0), "r"(a1), "r"(a2), "r"(a3), "r"(b0), "r"(b1));
}

__device__ __forceinline__ uint32_t smem_u32(const void* p) {
    return (uint32_t)__cvta_generic_to_shared(p);
}

#define CP_ASYNC16(dst_u32, src_ptr) \
    asm volatile("cp.async.cg.shared.global [%0], [%1], 16;" \
                 :: "r"(dst_u32), "l"(src_ptr))
#define CP_COMMIT() asm volatile("cp.async.commit_group;" ::: "memory")
#define CP_WAIT(n)  asm volatile("cp.async.wait_group %0;" :: "n"(n) : "memory")

// ===========================================================================
// tf32 tensor-core GEMM: C[M,N] = A[M,K] @ B[K,N] + bias[N]
// A row-major [M,K], B row-major [K,N] (native layouts, no transpose).
// 128x128 CTA tile, BK=32, 8 warps (2x4), warp tile 64x32,
// m16n8k8 tf32 mma, cp.async double buffering. 256 threads.
// Dynamic smem: As[2][128*36] + Bs[2][32*136] = 71,680 B.
// Requires M%128==0, N%128==0, K%32==0.
// ===========================================================================
#define BM 128
#define BN 128
#define BK 32
#define APAD 36    // As row stride (floats): 32 data + 4 pad (banks distinct)
#define BPAD 136   // Bs row stride (floats): 128 data + 8 pad (banks distinct)

#define GEMM_SMEM_BYTES ((2 * BM * APAD + 2 * BK * BPAD) * (int)sizeof(float))

__global__ __launch_bounds__(256) void mma_gemm_kernel(
    const float* __restrict__ A, const float* __restrict__ B,
    const float* __restrict__ bias, float* __restrict__ C,
    int M, int N, int K)
{
    extern __shared__ float smem[];
    float* AsBase = smem;                    // 2 stages of BM*APAD
    float* BsBase = smem + 2 * BM * APAD;    // 2 stages of BK*BPAD

    const int tid  = threadIdx.x;
    const int lane = tid & 31;
    const int wid  = tid >> 5;
    const int wm   = wid & 1;            // 0..1  (warp row)
    const int wn   = wid >> 1;           // 0..3  (warp col)
    const int m0   = blockIdx.y * BM;
    const int n0   = blockIdx.x * BN;

    // Fragment coordinates (PTX m16n8k8 tf32 thread mappings)
    const int aRow = wm * 64 + (lane >> 2);   // + mi*16 (+8)
    const int aCol = lane & 3;                 // + ks*8 (+4)
    const int bCol = wn * 32 + (lane >> 2);   // + ni*8
    const int bRow = lane & 3;                 // + ks*8 (+4)

    float acc[4][4][4];
    #pragma unroll
    for (int mi = 0; mi < 4; mi++)
        #pragma unroll
        for (int ni = 0; ni < 4; ni++)
            #pragma unroll
            for (int r = 0; r < 4; r++) acc[mi][ni][r] = 0.f;

    const int nch = K / BK;

    // --- async tile loader: stage s, chunk ch ---
    auto load_tiles = [&](int s, int ch) {
        const int k0 = ch * BK;
        float* As_ = AsBase + s * BM * APAD;
        float* Bs_ = BsBase + s * BK * BPAD;
        // A: 128 rows x 32 floats -> 1024 float4, 4 per thread
        #pragma unroll
        for (int i = 0; i < 4; i++) {
            const int idx = tid + i * 256;
            const int row = idx >> 3;
            const int c4  = (idx & 7) << 2;
            const float* src = A + (size_t)(m0 + row) * K + k0 + c4;
            CP_ASYNC16(smem_u32(&As_[row * APAD + c4]), src);
        }
        // B: 32 rows x 128 floats -> 1024 float4, 4 per thread
        #pragma unroll
        for (int i = 0; i < 4; i++) {
            const int idx = tid + i * 256;
            const int row = idx >> 5;
            const int c4  = (idx & 31) << 2;
            const float* src = B + (size_t)(k0 + row) * N + n0 + c4;
            CP_ASYNC16(smem_u32(&Bs_[row * BPAD + c4]), src);
        }
        CP_COMMIT();
    };

    load_tiles(0, 0);

    for (int ch = 0; ch < nch; ch++) {
        const int s = ch & 1;
        if (ch + 1 < nch) {
            load_tiles(s ^ 1, ch + 1);
            CP_WAIT(1);           // tiles for chunk ch are resident
        } else {
            CP_WAIT(0);
        }
        __syncthreads();

        const float* As_ = AsBase + s * BM * APAD;
        const float* Bs_ = BsBase + s * BK * BPAD;

        #pragma unroll
        for (int ks = 0; ks < 4; ks++) {
            const int k0 = ks * 8;
            uint32_t bf[4][2];
            #pragma unroll
            for (int ni = 0; ni < 4; ni++) {
                bf[ni][0] = f2tf32(Bs_[(k0 + bRow)     * BPAD + bCol + ni * 8]);
                bf[ni][1] = f2tf32(Bs_[(k0 + bRow + 4) * BPAD + bCol + ni * 8]);
            }
            #pragma unroll
            for (int mi = 0; mi < 4; mi++) {
                const int r0 = (aRow + mi * 16) * APAD;
                const int r8 = (aRow + mi * 16 + 8) * APAD;
                uint32_t a0 = f2tf32(As_[r0 + k0 + aCol]);
                uint32_t a1 = f2tf32(As_[r8 + k0 + aCol]);
                uint32_t a2 = f2tf32(As_[r0 + k0 + aCol + 4]);
                uint32_t a3 = f2tf32(As_[r8 + k0 + aCol + 4]);
                #pragma unroll
                for (int ni = 0; ni < 4; ni++)
                    mma_tf32_16x8x8(acc[mi][ni], a0, a1, a2, a3,
                                    bf[ni][0], bf[ni][1]);
            }
        }
        __syncthreads();   // compute done before next prefetch overwrites
    }

    // Epilogue: c0:(r,c) c1:(r,c+1) c2:(r+8,c) c3:(r+8,c+1)
    const int crow = m0 + wm * 64 + (lane >> 2);
    const int ccol = n0 + wn * 32 + ((lane & 3) << 1);
    #pragma unroll
    for (int mi = 0; mi < 4; mi++) {
        #pragma unroll
        for (int ni = 0; ni < 4; ni++) {
            const int col = ccol + ni * 8;
            const float bx = bias[col], by = bias[col + 1];
            float2 v0, v1;
            v0.x = acc[mi][ni][0] + bx;  v0.y = acc[mi][ni][1] + by;
            v1.x = acc[mi][ni][2] + bx;  v1.y = acc[mi][ni][3] + by;
            *(float2*)(C + (size_t)(crow + mi * 16)     * N + col) = v0;
            *(float2*)(C + (size_t)(crow + mi * 16 + 8) * N + col) = v1;
        }
    }
}

// ---------------------------------------------------------------------------
// Fused banded attention (flash-style), unchanged.
// ---------------------------------------------------------------------------
__global__ __launch_bounds__(256) void attn_kernel(
    const float* __restrict__ qkv, const int* __restrict__ pmask,
    float* __restrict__ ctx)
{
    extern __shared__ float sm[];
    float (*Qs)[65] = (float(*)[65])sm;                   // 64x65
    float (*Ks)[65] = (float(*)[65])(sm + 64 * 65);       // 64x65 (reused for P)
    float (*Vs)[65] = (float(*)[65])(sm + 2 * 64 * 65);   // 64x65
    __shared__ float m_sh[64], l_sh[64];

    const int tid = threadIdx.x;
    const int tx = tid & 15, ty = tid >> 4;
    const int r0 = blockIdx.x * 64;
    const int b  = blockIdx.y >> 3;
    const int h  = blockIdx.y & 7;

    const float* base = qkv + (size_t)b * SEQ * N1 + h * (3 * DHEAD);

    for (int idx = tid; idx < 64 * 16; idx += 256) {
        const int row = idx >> 4;
        const int c4  = (idx & 15) << 2;
        float4 v = *(const float4*)(base + (size_t)(r0 + row) * N1 + c4);
        Qs[row][c4 + 0] = v.x * 0.125f;
        Qs[row][c4 + 1] = v.y * 0.125f;
        Qs[row][c4 + 2] = v.z * 0.125f;
        Qs[row][c4 + 3] = v.w * 0.125f;
    }
    if (tid < 64) { m_sh[tid] = -1e30f; l_sh[tid] = 0.f; }

    float o[4][4];
    #pragma unroll
    for (int i = 0; i < 4; i++)
        #pragma unroll
        for (int j = 0; j < 4; j++) o[i][j] = 0.f;

    int gri[4];
    #pragma unroll
    for (int i = 0; i < 4; i++) gri[i] = r0 + ty * 4 + i;

    for (int kt = 0; kt < 5; kt++) {
        const int c0 = r0 - WINHALF + kt * 64;
        if (c0 + 63 < 0 || c0 >= SEQ) continue;

        __syncthreads();

        for (int idx = tid; idx < 64 * 16; idx += 256) {
            const int row = idx >> 4;
            const int c4  = (idx & 15) << 2;
            const int gc = c0 + row;
            float4 kv = make_float4(0.f, 0.f, 0.f, 0.f);
            float4 vv = make_float4(0.f, 0.f, 0.f, 0.f);
            if (gc >= 0 && gc < SEQ) {
                kv = *(const float4*)(base + (size_t)gc * N1 + DHEAD + c4);
                vv = *(const float4*)(base + (size_t)gc * N1 + 2 * DHEAD + c4);
            }
            Ks[row][c4 + 0] = kv.x; Ks[row][c4 + 1] = kv.y;
            Ks[row][c4 + 2] = kv.z; Ks[row][c4 + 3] = kv.w;
            Vs[row][c4 + 0] = vv.x; Vs[row][c4 + 1] = vv.y;
            Vs[row][c4 + 2] = vv.z; Vs[row][c4 + 3] = vv.w;
        }
        __syncthreads();

        float s[4][4];
        #pragma unroll
        for (int i = 0; i < 4; i++)
            #pragma unroll
            for (int j = 0; j < 4; j++) s[i][j] = 0.f;

        #pragma unroll 8
        for (int k = 0; k < 64; k++) {
            float ar[4], br[4];
            #pragma unroll
            for (int i = 0; i < 4; i++) ar[i] = Qs[ty * 4 + i][k];
            #pragma unroll
            for (int j = 0; j < 4; j++) br[j] = Ks[tx * 4 + j][k];
            #pragma unroll
            for (int i = 0; i < 4; i++)
                #pragma unroll
                for (int j = 0; j < 4; j++)
                    s[i][j] += ar[i] * br[j];
        }

        int gcj[4]; bool cv[4];
        #pragma unroll
        for (int j = 0; j < 4; j++) {
            gcj[j] = c0 + tx * 4 + j;
            cv[j] = (gcj[j] >= 0) && (gcj[j] < SEQ) &&
                    (pmask[b * SEQ + gcj[j]] == 1);
        }
        #pragma unroll
        for (int i = 0; i < 4; i++)
            #pragma unroll
            for (int j = 0; j < 4; j++) {
                const int d = gcj[j] - gri[i];
                if (!cv[j] || d > WINHALF || d < -WINHALF) s[i][j] = -1e30f;
            }

        float p[4][4];
        #pragma unroll
        for (int i = 0; i < 4; i++) {
            const int row = ty * 4 + i;
            float tm = fmaxf(fmaxf(s[i][0], s[i][1]), fmaxf(s[i][2], s[i][3]));
            #pragma unroll
            for (int off = 8; off >= 1; off >>= 1)
                tm = fmaxf(tm, __shfl_xor_sync(0xffffffffu, tm, off));
            const float mo = m_sh[row];
            const float mn = fmaxf(mo, tm);
            const float sc = __expf(mo - mn);
            float ts = 0.f;
            #pragma unroll
            for (int j = 0; j < 4; j++) {
                p[i][j] = (s[i][j] > -1e29f) ? __expf(s[i][j] - mn) : 0.f;
                ts += p[i][j];
            }
            #pragma unroll
            for (int off = 8; off >= 1; off >>= 1)
                ts += __shfl_xor_sync(0xffffffffu, ts, off);
            if (tx == 0) { m_sh[row] = mn; l_sh[row] = l_sh[row] * sc + ts; }
            #pragma unroll
            for (int j = 0; j < 4; j++) o[i][j] *= sc;
        }

        __syncthreads();
        #pragma unroll
        for (int i = 0; i < 4; i++)
            #pragma unroll
            for (int j = 0; j < 4; j++)
                Ks[ty * 4 + i][tx * 4 + j] = p[i][j];
        __syncthreads();

        #pragma unroll 8
        for (int c = 0; c < 64; c++) {
            float pr[4], vr[4];
            #pragma unroll
            for (int i = 0; i < 4; i++) pr[i] = Ks[ty * 4 + i][c];
            #pragma unroll
            for (int j = 0; j < 4; j++) vr[j] = Vs[c][tx * 4 + j];
            #pragma unroll
            for (int i = 0; i < 4; i++)
                #pragma unroll
                for (int j = 0; j < 4; j++)
                    o[i][j] += pr[i] * vr[j];
        }
    }
    __syncthreads();

    #pragma unroll
    for (int i = 0; i < 4; i++) {
        const int row = r0 + ty * 4 + i;
        const float l = l_sh[ty * 4 + i];
        const float inv = (l > 0.f && pmask[b * SEQ + row] == 1) ? 1.f / l : 0.f;
        float4 v;
        v.x = o[i][0] * inv; v.y = o[i][1] * inv;
        v.z = o[i][2] * inv; v.w = o[i][3] * inv;
        *(float4*)(ctx + (size_t)(b * SEQ + row) * EMB + h * DHEAD + tx * 4) = v;
    }
}

// ---------------------------------------------------------------------------
// Launch
// ---------------------------------------------------------------------------
extern "C" void kernel_launch(void* const* d_in, const int* in_sizes, int n_in,
                              void* d_out, int out_size)
{
    const float* x     = (const float*)d_in[0];
    const int*   pmask = (const int*)  d_in[1];
    const float* Wqkv  = (const float*)d_in[2];
    const float* bqkv  = (const float*)d_in[3];
    const float* Wo    = (const float*)d_in[4];
    const float* bo    = (const float*)d_in[5];
    float* out = (float*)d_out;

    float *qkv, *ctx;
    cudaGetSymbolAddress((void**)&qkv, g_qkv);
    cudaGetSymbolAddress((void**)&ctx, g_ctx);

    cudaFuncSetAttribute(mma_gemm_kernel,
                         cudaFuncAttributeMaxDynamicSharedMemorySize,
                         GEMM_SMEM_BYTES);

    // 1) QKV projection: [4096,512] @ [512,1536] + bqkv  (tf32 mma.sync)
    {
        dim3 grid(N1 / BN, M1 / BM);
        mma_gemm_kernel<<<grid, 256, GEMM_SMEM_BYTES>>>(x, Wqkv, bqkv, qkv,
                                                        M1, N1, KDIM);
    }

    // 2) Banded attention
    {
        const int smem = 3 * 64 * 65 * (int)sizeof(float);  // 49,920 B
        cudaFuncSetAttribute(attn_kernel,
                             cudaFuncAttributeMaxDynamicSharedMemorySize, smem);
        dim3 grid(SEQ / 64, BATCH * HEADS);
        attn_kernel<<<grid, 256, smem>>>(qkv, pmask, ctx);
    }

    // 3) Output projection: [4096,512] @ [512,512] + bo  (tf32 mma.sync)
    {
        dim3 grid(EMB / BN, M1 / BM);
        mma_gemm_kernel<<<grid, 256, GEMM_SMEM_BYTES>>>(ctx, Wo, bo, out,
                                                        M1, EMB, KDIM);
    }
}